// round 9
// baseline (speedup 1.0000x reference)
#include <cuda_runtime.h>
#include <cuda_fp16.h>
#include <math.h>

#define Bz 8
#define Tz 16
#define Sz 400
#define Hz 512
#define Cz 512
#define Ez 128
#define Vz 50000
#define VEz 50050

#define OUT_CTX  (Bz*Tz*VEz)
#define OUT_H    (OUT_CTX + Bz*Cz)
#define OUT_C    (OUT_H + Bz*Hz)
#define OUT_ATTN (OUT_C + Bz*Hz)
#define OUT_PGEN (OUT_ATTN + Bz*Tz*Sz)
#define OUT_COV  (OUT_PGEN + Bz)

// ---- device scratch ----
__device__ __half g_wt[(size_t)Hz*Vz];     // fp16 vocab weights, transposed [k][j]
__device__ float g_encp[Bz*Sz*Hz];
__device__ float g_h2[2][Bz*Hz];
__device__ float g_c2[2][Bz*Hz];
__device__ float g_x3[3][Bz*Ez];
__device__ float g_ctx2[2][Bz*Cz];
__device__ float g_probs2[2][Bz*Sz];
__device__ float g_attnd2[2][Bz*Hz];
__device__ float g_pgen2[2][Bz];
__device__ float g_cov[Bz*Sz];
__device__ float g_hp[Bz*Hz];
__device__ float g_e[Bz*Sz];
__device__ float g_bsum[Tz][Bz];
__device__ unsigned g_barA, g_barV;

__device__ __forceinline__ float sigmoidf_(float x){ return 1.f/(1.f+expf(-x)); }

// proven grid-subgroup barrier: full fences, single arrive, ld.cv poll
__device__ __forceinline__ void gsync(unsigned* bar, unsigned target){
    __threadfence();
    __syncthreads();
    if (threadIdx.x == 0){
        atomicAdd(bar, 1u);
        unsigned v;
        for (;;){
            asm volatile("ld.global.cv.u32 %0, [%1];" : "=r"(v) : "l"(bar) : "memory");
            if (v >= target) break;
            __nanosleep(32);
        }
    }
    __syncthreads();
    __threadfence();
}

// ---- init ----
__global__ void k_init(const float* __restrict__ h0, const float* __restrict__ c0,
                       const float* __restrict__ ctx, const float* __restrict__ cov){
    int i = blockIdx.x*blockDim.x + threadIdx.x;
    if (i < Bz*Hz){ g_h2[1][i] = h0[i]; g_c2[1][i] = c0[i]; }
    if (i < Bz*Cz)  g_ctx2[1][i] = ctx[i];
    if (i < Bz*Sz)  g_cov[i] = cov[i];
    if (i == 0){ g_barA = 0u; g_barV = 0u; }
    if (i < Tz*Bz) ((float*)g_bsum)[i] = 0.f;
}

// ==== fused precompute: encproj(0..199) | transpose(200..303) | zero(304..335) | x0(336..367) ====
__global__ __launch_bounds__(256) void k_pre(const float* __restrict__ enc,
                                             const float* __restrict__ ew,
                                             const float* __restrict__ eb,
                                             const float* __restrict__ vw,
                                             const float* __restrict__ emb,
                                             const float* __restrict__ xw,
                                             const float* __restrict__ xb,
                                             float* __restrict__ out){
    int tid = threadIdx.x, bid = blockIdx.x;
    if (bid < 200){
        // ---- enc_proj GEMM: [3200,512] = enc * ew[:,H:]^T + eb ----
        __shared__ float As[16][128];
        __shared__ float Bs[16][64];
        int bm = (bid % 25) * 128;
        int bn = (bid / 25) * 64;
        float acc[8][4] = {};
        for (int k0 = 0; k0 < 512; k0 += 16){
#pragma unroll
            for (int r = 0; r < 2; r++){
                int id = tid + r*256;
                int m  = id >> 2;
                int kq = (id & 3) * 4;
                float4 v = *(const float4*)(enc + (size_t)(bm+m)*512 + k0 + kq);
                As[kq  ][m] = v.x; As[kq+1][m] = v.y; As[kq+2][m] = v.z; As[kq+3][m] = v.w;
            }
            {
                int n  = tid >> 2;
                int kq = (tid & 3) * 4;
                float4 v = *(const float4*)(ew + (size_t)(bn+n)*1024 + 512 + k0 + kq);
                Bs[kq  ][n] = v.x; Bs[kq+1][n] = v.y; Bs[kq+2][n] = v.z; Bs[kq+3][n] = v.w;
            }
            __syncthreads();
            int tm = (tid >> 4) * 8, tn = (tid & 15) * 4;
#pragma unroll
            for (int kk = 0; kk < 16; kk++){
                float a[8], bb[4];
                *(float4*)&a[0] = *(const float4*)&As[kk][tm];
                *(float4*)&a[4] = *(const float4*)&As[kk][tm+4];
                *(float4*)&bb[0] = *(const float4*)&Bs[kk][tn];
#pragma unroll
                for (int i = 0; i < 8; i++)
#pragma unroll
                    for (int j = 0; j < 4; j++) acc[i][j] += a[i]*bb[j];
            }
            __syncthreads();
        }
        int tm = (tid >> 4) * 8, tn = (tid & 15) * 4;
#pragma unroll
        for (int i = 0; i < 8; i++)
#pragma unroll
            for (int j = 0; j < 4; j++)
                g_encp[(size_t)(bm+tm+i)*512 + bn+tn+j] = acc[i][j] + eb[bn+tn+j];
    } else if (bid < 304){
        // ---- transpose vocab_w (V x H) fp32 -> g_wt (H x V) fp16 ----
        __shared__ float tile[32][33];
        int tx = tid & 31, ty = tid >> 5;
        const int NTILE = ((Vz + 31)/32) * (Hz/32);   // 1563*16 = 25008
        for (int T = bid - 200; T < NTILE; T += 104){
            int jb = (T % 1563)*32, kb = (T / 1563)*32;
            __syncthreads();
#pragma unroll
            for (int r = 0; r < 32; r += 8){
                int jj = jb + ty + r;
                if (jj < Vz) tile[ty + r][tx] = vw[(size_t)jj*Hz + kb + tx];
            }
            __syncthreads();
#pragma unroll
            for (int r = 0; r < 32; r += 8){
                int kk = kb + ty + r;
                int jj = jb + tx;
                if (jj < Vz) g_wt[(size_t)kk*Vz + jj] = __float2half(tile[tx][ty + r]);
            }
        }
    } else if (bid < 336){
        // ---- zero FVD region ----
        float4* o4 = (float4*)out;
        for (size_t i = (size_t)(bid - 304)*256 + tid; i < (size_t)Bz*Tz*VEz/4; i += 32*256)
            o4[i] = make_float4(0.f,0.f,0.f,0.f);
    } else {
        // ---- x for t=0 ----
        int xbid = bid - 336;
        int b = xbid >> 2;
        int warp = tid >> 5, lane = tid & 31;
        __shared__ float vec[640];
        for (int i = tid; i < 128; i += 256) vec[i] = emb[(size_t)b*Tz*Ez + i];
        for (int i = tid; i < 512; i += 256) vec[128 + i] = g_ctx2[1][b*Cz + i];
        __syncthreads();
#pragma unroll
        for (int q = 0; q < 4; q++){
            int j = (xbid & 3)*32 + warp*4 + q;
            const float* w = xw + (size_t)j*640;
            float acc = 0.f;
#pragma unroll
            for (int i = 0; i < 20; i++){ int k = lane + 32*i; acc += w[k]*vec[k]; }
#pragma unroll
            for (int off = 16; off; off >>= 1) acc += __shfl_xor_sync(~0u, acc, off);
            if (lane == 0) g_x3[0][b*Ez + j] = acc + xb[j];
        }
    }
}

// ==== pipelined step kernel: blocks 0..63 = A(t); 64..161 = V(t-1) ====
__global__ __launch_bounds__(256, 2) void k_step(
        const float* __restrict__ Wih, const float* __restrict__ Whh,
        const float* __restrict__ bih, const float* __restrict__ bhh,
        const float* __restrict__ ew,  const float* __restrict__ covw,
        const float* __restrict__ vv,  const float* __restrict__ enc,
        const float* __restrict__ mask,
        const float* __restrict__ aw,  const float* __restrict__ ab,
        const float* __restrict__ pw,  const float* __restrict__ pb,
        const float* __restrict__ xw,  const float* __restrict__ xb,
        const float* __restrict__ emb, const float* __restrict__ vb,
        const int*   __restrict__ sidx,
        float* __restrict__ out, int t){
    __shared__ __align__(16) float sU[5248];
    __shared__ float red[40];
    __shared__ float red2[8][8];
    __shared__ float smv[8];
    int tid = threadIdx.x, warp = tid >> 5, lane = tid & 31, bid = blockIdx.x;

    if (bid < 64){
        // =============== group A: recurrence step t ===============
        if (t < Tz){
            const float* xin  = g_x3[t % 3];
            float*       xout = g_x3[(t + 1) % 3];
            const float* hin  = g_h2[(t + 1) & 1];
            float*       hout = g_h2[t & 1];
            const float* cin  = g_c2[(t + 1) & 1];
            float*       cout = g_c2[t & 1];
            float*       ctxo = g_ctx2[t & 1];
            float*       pro  = g_probs2[t & 1];
            float*       atd  = g_attnd2[t & 1];
            float*       pgo  = g_pgen2[t & 1];

            // ---- P1: gates + LSTM elementwise ----
            {
                float* sx = sU;
                float* sh = sU + 1024;
                for (int i = tid; i < Bz*Ez; i += 256) sx[i] = __ldcg(&xin[i]);
                for (int i = tid; i < Bz*Hz; i += 256) sh[i] = __ldcg(&hin[i]);
                __syncthreads();
                int j = bid*8 + warp;
                float acc[4][8] = {};
#pragma unroll
                for (int q = 0; q < 4; q++){
                    const float* wi = Wih + (size_t)(q*Hz + j)*Ez;
#pragma unroll
                    for (int i2 = 0; i2 < 4; i2++){
                        int k = lane + 32*i2; float w = wi[k];
#pragma unroll
                        for (int b = 0; b < 8; b++) acc[q][b] += w * sx[b*Ez + k];
                    }
                    const float* wh = Whh + (size_t)(q*Hz + j)*Hz;
#pragma unroll
                    for (int i2 = 0; i2 < 16; i2++){
                        int k = lane + 32*i2; float w = wh[k];
#pragma unroll
                        for (int b = 0; b < 8; b++) acc[q][b] += w * sh[b*Hz + k];
                    }
                }
#pragma unroll
                for (int off = 16; off; off >>= 1)
#pragma unroll
                    for (int q = 0; q < 4; q++)
#pragma unroll
                        for (int b = 0; b < 8; b++) acc[q][b] += __shfl_xor_sync(~0u, acc[q][b], off);
                if (lane < 8){
                    int b = lane;
                    float gi = acc[0][b] + bih[j]        + bhh[j];
                    float gf = acc[1][b] + bih[Hz + j]   + bhh[Hz + j];
                    float gg = acc[2][b] + bih[2*Hz + j] + bhh[2*Hz + j];
                    float go = acc[3][b] + bih[3*Hz + j] + bhh[3*Hz + j];
                    float cn = sigmoidf_(gf)*__ldcg(&cin[b*Hz + j]) + sigmoidf_(gi)*tanhf(gg);
                    float hn = sigmoidf_(go)*tanhf(cn);
                    __stcg(&cout[b*Hz + j], cn);
                    __stcg(&hout[b*Hz + j], hn);
                }
            }
            gsync(&g_barA, (unsigned)(4*t + 1) * 64u);

            // ---- P2: hp ----
            {
                float* sh = sU;
                for (int i = tid; i < Bz*Hz; i += 256) sh[i] = __ldcg(&hout[i]);
                __syncthreads();
                int j = bid*8 + warp;
                const float* w = ew + (size_t)j*1024;
                float acc[8] = {};
#pragma unroll
                for (int i2 = 0; i2 < 16; i2++){
                    int k = lane + 32*i2; float wv = w[k];
#pragma unroll
                    for (int b = 0; b < 8; b++) acc[b] += wv * sh[b*Hz + k];
                }
#pragma unroll
                for (int off = 16; off; off >>= 1)
#pragma unroll
                    for (int b = 0; b < 8; b++) acc[b] += __shfl_xor_sync(~0u, acc[b], off);
                if (lane < 8) __stcg(&g_hp[lane*Hz + j], acc[lane]);
            }
            gsync(&g_barA, (unsigned)(4*t + 2) * 64u);

            // ---- P3: energies + zero ctx chunk ----
            {
                float* sh = sU;
                int b = bid >> 3, sc = bid & 7;
                for (int i = tid; i < Hz; i += 256){
                    sh[i]        = __ldcg(&g_hp[b*Hz + i]);
                    sh[Hz + i]   = covw[i];
                    sh[2*Hz + i] = vv[i];
                }
                if (tid < 64) __stcg(&ctxo[bid*64 + tid], 0.f);
                __syncthreads();
                int s0 = sc*50;
#pragma unroll
                for (int r = 0; r < 7; r++){
                    int sl = warp + 8*r;
                    if (sl < 50){
                        int s = s0 + sl;
                        float cb = __ldcg(&g_cov[b*Sz + s]);
                        const float* ep = g_encp + ((size_t)(b*Sz + s))*Hz;
                        float acc = 0.f;
#pragma unroll
                        for (int i2 = 0; i2 < 16; i2++){
                            int k = lane + 32*i2;
                            acc += sh[2*Hz + k] * tanhf(sh[k] + ep[k] + cb*sh[Hz + k]);
                        }
#pragma unroll
                        for (int off = 16; off; off >>= 1) acc += __shfl_xor_sync(~0u, acc, off);
                        if (lane == 0) __stcg(&g_e[b*Sz + s], acc);
                    }
                }
            }
            gsync(&g_barA, (unsigned)(4*t + 3) * 64u);

            // ---- P45: redundant softmax + slice writes + ctx partials ----
            {
                int b = bid >> 3, sc = bid & 7;
                float* se = sU;
                float* sp = sU + 512;
                se[tid] = __ldcg(&g_e[b*Sz + tid]);
                if (tid + 256 < Sz) se[tid + 256] = __ldcg(&g_e[b*Sz + tid + 256]);
                __syncthreads();
                float e0 = se[tid];
                float e1 = (tid + 256 < Sz) ? se[tid + 256] : -1e30f;
                float lm = fmaxf(e0, e1);
#pragma unroll
                for (int off = 16; off; off >>= 1) lm = fmaxf(lm, __shfl_xor_sync(~0u, lm, off));
                if (lane == 0) red[warp] = lm;
                __syncthreads();
                if (tid == 0){ float m = red[0]; for (int w = 1; w < 8; w++) m = fmaxf(m, red[w]); red[32] = m; }
                __syncthreads();
                float m = red[32];
                float x0 = expf(e0 - m);
                float x1 = (tid + 256 < Sz) ? expf(e1 - m) : 0.f;
                float ls = x0 + x1;
#pragma unroll
                for (int off = 16; off; off >>= 1) ls += __shfl_xor_sync(~0u, ls, off);
                if (lane == 0) red[warp] = ls;
                __syncthreads();
                if (tid == 0){ float s = 0.f; for (int w = 0; w < 8; w++) s += red[w]; red[33] = s; }
                __syncthreads();
                float s1 = red[33];
                float pm0 = x0/s1 * mask[b*Sz + tid];
                float pm1 = (tid + 256 < Sz) ? x1/s1 * mask[b*Sz + tid + 256] : 0.f;
                ls = pm0 + pm1;
#pragma unroll
                for (int off = 16; off; off >>= 1) ls += __shfl_xor_sync(~0u, ls, off);
                if (lane == 0) red[warp] = ls;
                __syncthreads();
                if (tid == 0){ float s = 0.f; for (int w = 0; w < 8; w++) s += red[w]; red[34] = s; }
                __syncthreads();
                float inv = 1.f/(red[34] + 1e-12f);
                if (tid < 50){
                    int s = sc*50 + tid;
                    float pr = expf(se[s] - m)/s1 * mask[b*Sz + s] * inv;
                    sp[tid] = pr;
                    __stcg(&pro[b*Sz + s], pr);
                    out[OUT_ATTN + ((size_t)b*Tz + t)*Sz + s] = pr;
                    float cn = __ldcg(&g_cov[b*Sz + s]) + pr;
                    __stcg(&g_cov[b*Sz + s], cn);
                    out[OUT_COV + ((size_t)b*Tz + t)*Sz + s] = cn;
                }
                __syncthreads();
                const float* eo = enc + ((size_t)(b*Sz) + sc*50)*Cz;
                float a0 = 0.f, a1 = 0.f;
#pragma unroll 10
                for (int s = 0; s < 50; s++){
                    float pv = sp[s];
                    a0 += pv * eo[(size_t)s*Cz + tid];
                    a1 += pv * eo[(size_t)s*Cz + tid + 256];
                }
                atomicAdd(&ctxo[b*Cz + tid], a0);
                atomicAdd(&ctxo[b*Cz + tid + 256], a1);
            }
            gsync(&g_barA, (unsigned)(4*t + 4) * 64u);

            // ---- P6: xnext (0..7) | pgen (8..15) | attnd (16..47) ----
            if (bid < 8){
                if (t + 1 < Tz){
                    int b = bid;
                    for (int i = tid; i < 512; i += 256) sU[128 + i] = __ldcg(&ctxo[b*Cz + i]);
                    if (tid < 128) sU[tid] = emb[((size_t)b*Tz + t + 1)*Ez + tid];
                    __syncthreads();
#pragma unroll
                    for (int q = 0; q < 16; q++){
                        int j = warp*16 + q;
                        const float* w = xw + (size_t)j*640;
                        float acc = 0.f;
#pragma unroll
                        for (int i2 = 0; i2 < 20; i2++){ int k = lane + 32*i2; acc += w[k]*sU[k]; }
#pragma unroll
                        for (int off = 16; off; off >>= 1) acc += __shfl_xor_sync(~0u, acc, off);
                        if (lane == 0) __stcg(&xout[b*Ez + j], acc + xb[j]);
                    }
                }
            } else if (bid < 16){
                int b = bid - 8;
                float z = __ldcg(&ctxo[b*Cz + tid])*pw[tid] + __ldcg(&ctxo[b*Cz + tid + 256])*pw[tid + 256]
                        + __ldcg(&hout[b*Hz + tid])*pw[512 + tid] + __ldcg(&hout[b*Hz + tid + 256])*pw[768 + tid];
                if (tid < 128) z += __ldcg(&xin[b*Ez + tid])*pw[1024 + tid];
#pragma unroll
                for (int off = 16; off; off >>= 1) z += __shfl_xor_sync(~0u, z, off);
                if (lane == 0) red[warp] = z;
                __syncthreads();
                if (tid == 0){
                    float s = 0.f; for (int w = 0; w < 8; w++) s += red[w];
                    float pg = sigmoidf_(s + pb[0]);
                    __stcg(&pgo[b], pg);
                    if (t == Tz - 1) out[OUT_PGEN + b] = pg;
                }
            } else if (bid < 48){
                int ab2 = bid - 16;
                int b = ab2 >> 2;
                for (int i = tid; i < 512; i += 256) sU[i]       = __ldcg(&hout[b*Hz + i]);
                for (int i = tid; i < 512; i += 256) sU[512 + i] = __ldcg(&ctxo[b*Cz + i]);
                __syncthreads();
                int r0 = (ab2 & 3)*128 + warp*16;
#pragma unroll
                for (int q = 0; q < 16; q++){
                    int j = r0 + q;
                    const float* w = aw + (size_t)j*1024;
                    float acc = 0.f;
#pragma unroll
                    for (int i2 = 0; i2 < 32; i2++){ int k = lane + 32*i2; acc += w[k]*sU[k]; }
#pragma unroll
                    for (int off = 16; off; off >>= 1) acc += __shfl_xor_sync(~0u, acc, off);
                    if (lane == 0) __stcg(&atd[b*Hz + j], acc + ab[j]);
                }
            }
        } else {
            // t == Tz: final states
            if (bid < 16){
                int i = bid*256 + tid;
                out[OUT_CTX + i] = __ldcg(&g_ctx2[1][i]);
                out[OUT_H + i]   = __ldcg(&g_h2[1][i]);
                out[OUT_C + i]   = __ldcg(&g_c2[1][i]);
            }
        }
    } else {
        // =============== group V: vocab pipeline for u = t-1 (98 blocks, 2 cols/thread) ===============
        if (t >= 1){
            int u = t - 1;
            int vbid = bid - 64;
            const float* pro = g_probs2[u & 1];
            const float* atd = g_attnd2[u & 1];
            const float* pgi = g_pgen2[u & 1];

            // Ph1: vocab GEMV (fp16 weights, half2) + exp + sum
            float4* a4 = (float4*)sU;
            {
                const float4* src = (const float4*)atd;
#pragma unroll
                for (int r = 0; r < 4; r++) a4[tid + r*256] = __ldcg(&src[tid + r*256]);
            }
            __syncthreads();
            int j0 = vbid*512 + tid*2;
            bool valid = j0 < Vz;
            float acc0[Bz], acc1[Bz];
            {
                float b0 = valid ? vb[j0] : 0.f;
                float b1 = valid ? vb[j0 + 1] : 0.f;
#pragma unroll
                for (int b = 0; b < Bz; b++){ acc0[b] = b0; acc1[b] = b1; }
            }
            {
                const __half* wp = g_wt + (valid ? j0 : 0);
#pragma unroll 4
                for (int kk = 0; kk < 128; kk++){
                    float2 f0 = __half22float2(*(const __half2*)(wp));
                    float2 f1 = __half22float2(*(const __half2*)(wp + Vz));
                    float2 f2 = __half22float2(*(const __half2*)(wp + 2*(size_t)Vz));
                    float2 f3 = __half22float2(*(const __half2*)(wp + 3*(size_t)Vz));
                    wp += 4*(size_t)Vz;
#pragma unroll
                    for (int b = 0; b < Bz; b++){
                        float4 a = a4[(size_t)b*128 + kk];
                        acc0[b] += f0.x*a.x + f1.x*a.y + f2.x*a.z + f3.x*a.w;
                        acc1[b] += f0.y*a.x + f1.y*a.y + f2.y*a.z + f3.y*a.w;
                    }
                }
            }
#pragma unroll
            for (int b = 0; b < Bz; b++){
                acc0[b] = valid ? expf(acc0[b]) : 0.f;
                acc1[b] = valid ? expf(acc1[b]) : 0.f;
            }
#pragma unroll
            for (int b = 0; b < Bz; b++){
                float s = acc0[b] + acc1[b];
#pragma unroll
                for (int off = 16; off; off >>= 1) s += __shfl_xor_sync(~0u, s, off);
                if (lane == 0) red2[b][warp] = s;
            }
            __syncthreads();
            if (tid < 8){
                float s = 0.f;
#pragma unroll
                for (int w = 0; w < 8; w++) s += red2[tid][w];
                atomicAdd(&g_bsum[u][tid], s);
            }
            gsync(&g_barV, (unsigned)(u + 1) * 98u);

            // Ph2: atomic add of normalized dist + copy scatter
            if (tid < 8) smv[tid] = __ldcg(&pgi[tid]) / __ldcg(&g_bsum[u][tid]);
            __syncthreads();
            if (valid){
#pragma unroll
                for (int b = 0; b < Bz; b++){
                    float* row = out + ((size_t)(b*Tz + u))*VEz;
                    atomicAdd(row + j0,     acc0[b] * smv[b]);
                    atomicAdd(row + j0 + 1, acc1[b] * smv[b]);
                }
            }
            if (vbid < 8){
                int b = vbid;
                float om = 1.f - __ldcg(&pgi[b]);
                float* row = out + ((size_t)(b*Tz + u))*VEz;
                for (int s = tid; s < Sz; s += 256)
                    atomicAdd(row + sidx[b*Sz + s], om * __ldcg(&pro[b*Sz + s]));
            }
        }
    }
}

extern "C" void kernel_launch(void* const* d_in, const int* in_sizes, int n_in,
                              void* d_out, int out_size){
    const float* emb   = (const float*)d_in[0];
    const float* ctx0  = (const float*)d_in[1];
    const float* h0    = (const float*)d_in[2];
    const float* c0    = (const float*)d_in[3];
    const float* enc   = (const float*)d_in[4];
    const float* mask  = (const float*)d_in[5];
    const int*   sidx  = (const int*)  d_in[7];
    const float* cov0  = (const float*)d_in[8];
    const float* Wih   = (const float*)d_in[9];
    const float* Whh   = (const float*)d_in[10];
    const float* bih   = (const float*)d_in[11];
    const float* bhh   = (const float*)d_in[12];
    const float* covw  = (const float*)d_in[13];
    const float* ew    = (const float*)d_in[14];
    const float* eb    = (const float*)d_in[15];
    const float* vvec  = (const float*)d_in[16];
    const float* xw    = (const float*)d_in[17];
    const float* xb    = (const float*)d_in[18];
    const float* aw    = (const float*)d_in[19];
    const float* ab    = (const float*)d_in[20];
    const float* vw    = (const float*)d_in[21];
    const float* vb    = (const float*)d_in[22];
    const float* pw    = (const float*)d_in[23];
    const float* pb    = (const float*)d_in[24];
    float* out = (float*)d_out;

    // Precompute: init, then one fused launch (encproj || transpose || zero || x0)
    k_init<<<32, 512>>>(h0, c0, ctx0, cov0);
    k_pre<<<368, 256>>>(enc, ew, eb, vw, emb, xw, xb, out);

    // Pipelined steps: launch t computes A(t) and V(t-1) concurrently
    for (int t = 0; t <= Tz; t++){
        k_step<<<162, 256>>>(Wih, Whh, bih, bhh, ew, covw, vvec, enc, mask,
                             aw, ab, pw, pb, xw, xb, emb, vb, sidx, out, t);
    }
}

// round 10
// speedup vs baseline: 1.0225x; 1.0225x over previous
#include <cuda_runtime.h>
#include <cuda_fp16.h>
#include <math.h>

#define Bz 8
#define Tz 16
#define Sz 400
#define Hz 512
#define Cz 512
#define Ez 128
#define Vz 50000
#define VEz 50050

#define OUT_CTX  (Bz*Tz*VEz)
#define OUT_H    (OUT_CTX + Bz*Cz)
#define OUT_C    (OUT_H + Bz*Hz)
#define OUT_ATTN (OUT_C + Bz*Hz)
#define OUT_PGEN (OUT_ATTN + Bz*Tz*Sz)
#define OUT_COV  (OUT_PGEN + Bz)

// ---- device scratch ----
// packed fp16 vocab weights: g_wt4[(k/8)*Vz + j] = {w[k][j], w[k+1][j], ..., w[k+7][j]}
__device__ uint4 g_wt4[(size_t)(Hz/8)*Vz];
__device__ float g_encp[Bz*Sz*Hz];
__device__ float g_h2[2][Bz*Hz];
__device__ float g_c2[2][Bz*Hz];
__device__ float g_x3[3][Bz*Ez];
__device__ float g_ctx2[2][Bz*Cz];
__device__ float g_probs2[2][Bz*Sz];
__device__ float g_attnd2[2][Bz*Hz];
__device__ float g_pgen2[2][Bz];
__device__ float g_cov[Bz*Sz];
__device__ float g_hp[Bz*Hz];
__device__ float g_e[Bz*Sz];
__device__ float g_bsum[Tz][Bz];
__device__ unsigned g_barA, g_barV;

__device__ __forceinline__ float sigmoidf_(float x){ return 1.f/(1.f+expf(-x)); }

// proven grid-subgroup barrier
__device__ __forceinline__ void gsync(unsigned* bar, unsigned target){
    __threadfence();
    __syncthreads();
    if (threadIdx.x == 0){
        atomicAdd(bar, 1u);
        unsigned v;
        for (;;){
            asm volatile("ld.global.cv.u32 %0, [%1];" : "=r"(v) : "l"(bar) : "memory");
            if (v >= target) break;
            __nanosleep(32);
        }
    }
    __syncthreads();
    __threadfence();
}

// ---- init ----
__global__ void k_init(const float* __restrict__ h0, const float* __restrict__ c0,
                       const float* __restrict__ ctx, const float* __restrict__ cov){
    int i = blockIdx.x*blockDim.x + threadIdx.x;
    if (i < Bz*Hz){ g_h2[1][i] = h0[i]; g_c2[1][i] = c0[i]; }
    if (i < Bz*Cz)  g_ctx2[1][i] = ctx[i];
    if (i < Bz*Sz)  g_cov[i] = cov[i];
    if (i == 0){ g_barA = 0u; g_barV = 0u; }
    if (i < Tz*Bz) ((float*)g_bsum)[i] = 0.f;
}

// ==== fused precompute: encproj(0..199) | transpose->packed fp16(200..303) | zero(304..335) | x0(336..367) ====
__global__ __launch_bounds__(256) void k_pre(const float* __restrict__ enc,
                                             const float* __restrict__ ew,
                                             const float* __restrict__ eb,
                                             const float* __restrict__ vw,
                                             const float* __restrict__ emb,
                                             const float* __restrict__ xw,
                                             const float* __restrict__ xb,
                                             float* __restrict__ out){
    int tid = threadIdx.x, bid = blockIdx.x;
    if (bid < 200){
        __shared__ float As[16][128];
        __shared__ float Bs[16][64];
        int bm = (bid % 25) * 128;
        int bn = (bid / 25) * 64;
        float acc[8][4] = {};
        for (int k0 = 0; k0 < 512; k0 += 16){
#pragma unroll
            for (int r = 0; r < 2; r++){
                int id = tid + r*256;
                int m  = id >> 2;
                int kq = (id & 3) * 4;
                float4 v = *(const float4*)(enc + (size_t)(bm+m)*512 + k0 + kq);
                As[kq  ][m] = v.x; As[kq+1][m] = v.y; As[kq+2][m] = v.z; As[kq+3][m] = v.w;
            }
            {
                int n  = tid >> 2;
                int kq = (tid & 3) * 4;
                float4 v = *(const float4*)(ew + (size_t)(bn+n)*1024 + 512 + k0 + kq);
                Bs[kq  ][n] = v.x; Bs[kq+1][n] = v.y; Bs[kq+2][n] = v.z; Bs[kq+3][n] = v.w;
            }
            __syncthreads();
            int tm = (tid >> 4) * 8, tn = (tid & 15) * 4;
#pragma unroll
            for (int kk = 0; kk < 16; kk++){
                float a[8], bb[4];
                *(float4*)&a[0] = *(const float4*)&As[kk][tm];
                *(float4*)&a[4] = *(const float4*)&As[kk][tm+4];
                *(float4*)&bb[0] = *(const float4*)&Bs[kk][tn];
#pragma unroll
                for (int i = 0; i < 8; i++)
#pragma unroll
                    for (int j = 0; j < 4; j++) acc[i][j] += a[i]*bb[j];
            }
            __syncthreads();
        }
        int tm = (tid >> 4) * 8, tn = (tid & 15) * 4;
#pragma unroll
        for (int i = 0; i < 8; i++)
#pragma unroll
            for (int j = 0; j < 4; j++)
                g_encp[(size_t)(bm+tm+i)*512 + bn+tn+j] = acc[i][j] + eb[bn+tn+j];
    } else if (bid < 304){
        // ---- transpose vocab_w (V x H) fp32 -> packed fp16 g_wt4 ----
        __shared__ float tile[32][33];
        int tx = tid & 31, ty = tid >> 5;
        const int NTILE = ((Vz + 31)/32) * (Hz/32);
        for (int T = bid - 200; T < NTILE; T += 104){
            int jb = (T % 1563)*32, kb = (T / 1563)*32;
            __syncthreads();
#pragma unroll
            for (int r = 0; r < 32; r += 8){
                int jj = jb + ty + r;
                if (jj < Vz) tile[ty + r][tx] = vw[(size_t)jj*Hz + kb + tx];
            }
            __syncthreads();
            // assemble uint4 per (j, k-group of 8): 32 j x 4 kgroups = 128 threads
            if (tid < 128){
                int jl = tid & 31, kgl = tid >> 5;
                int jj = jb + jl;
                if (jj < Vz){
                    __half hv[8];
#pragma unroll
                    for (int r = 0; r < 8; r++) hv[r] = __float2half(tile[jl][kgl*8 + r]);
                    g_wt4[((size_t)(kb/8) + kgl)*Vz + jj] = *(const uint4*)hv;
                }
            }
        }
    } else if (bid < 336){
        float4* o4 = (float4*)out;
        for (size_t i = (size_t)(bid - 304)*256 + tid; i < (size_t)Bz*Tz*VEz/4; i += 32*256)
            o4[i] = make_float4(0.f,0.f,0.f,0.f);
    } else {
        int xbid = bid - 336;
        int b = xbid >> 2;
        int warp = tid >> 5, lane = tid & 31;
        __shared__ float vec[640];
        for (int i = tid; i < 128; i += 256) vec[i] = emb[(size_t)b*Tz*Ez + i];
        for (int i = tid; i < 512; i += 256) vec[128 + i] = g_ctx2[1][b*Cz + i];
        __syncthreads();
#pragma unroll
        for (int q = 0; q < 4; q++){
            int j = (xbid & 3)*32 + warp*4 + q;
            const float* w = xw + (size_t)j*640;
            float acc = 0.f;
#pragma unroll
            for (int i = 0; i < 20; i++){ int k = lane + 32*i; acc += w[k]*vec[k]; }
#pragma unroll
            for (int off = 16; off; off >>= 1) acc += __shfl_xor_sync(~0u, acc, off);
            if (lane == 0) g_x3[0][b*Ez + j] = acc + xb[j];
        }
    }
}

// ==== pipelined step kernel: blocks 0..63 = A(t); 64..259 = V(t-1) ====
__global__ __launch_bounds__(256, 2) void k_step(
        const float* __restrict__ Wih, const float* __restrict__ Whh,
        const float* __restrict__ bih, const float* __restrict__ bhh,
        const float* __restrict__ ew,  const float* __restrict__ covw,
        const float* __restrict__ vv,  const float* __restrict__ enc,
        const float* __restrict__ mask,
        const float* __restrict__ aw,  const float* __restrict__ ab,
        const float* __restrict__ pw,  const float* __restrict__ pb,
        const float* __restrict__ xw,  const float* __restrict__ xb,
        const float* __restrict__ emb, const float* __restrict__ vb,
        const int*   __restrict__ sidx,
        float* __restrict__ out, int t){
    __shared__ __align__(16) float sU[5248];
    __shared__ float red[40];
    __shared__ float red2[8][8];
    __shared__ float smv[8];
    int tid = threadIdx.x, warp = tid >> 5, lane = tid & 31, bid = blockIdx.x;

    if (bid < 64){
        // =============== group A: recurrence step t ===============
        if (t < Tz){
            const float* xin  = g_x3[t % 3];
            float*       xout = g_x3[(t + 1) % 3];
            const float* hin  = g_h2[(t + 1) & 1];
            float*       hout = g_h2[t & 1];
            const float* cin  = g_c2[(t + 1) & 1];
            float*       cout = g_c2[t & 1];
            float*       ctxo = g_ctx2[t & 1];
            float*       pro  = g_probs2[t & 1];
            float*       atd  = g_attnd2[t & 1];
            float*       pgo  = g_pgen2[t & 1];

            // ---- P1: gates + LSTM elementwise ----
            {
                float* sx = sU;
                float* sh = sU + 1024;
                for (int i = tid; i < Bz*Ez; i += 256) sx[i] = __ldcg(&xin[i]);
                for (int i = tid; i < Bz*Hz; i += 256) sh[i] = __ldcg(&hin[i]);
                __syncthreads();
                int j = bid*8 + warp;
                float acc[4][8] = {};
#pragma unroll
                for (int q = 0; q < 4; q++){
                    const float* wi = Wih + (size_t)(q*Hz + j)*Ez;
#pragma unroll
                    for (int i2 = 0; i2 < 4; i2++){
                        int k = lane + 32*i2; float w = wi[k];
#pragma unroll
                        for (int b = 0; b < 8; b++) acc[q][b] += w * sx[b*Ez + k];
                    }
                    const float* wh = Whh + (size_t)(q*Hz + j)*Hz;
#pragma unroll
                    for (int i2 = 0; i2 < 16; i2++){
                        int k = lane + 32*i2; float w = wh[k];
#pragma unroll
                        for (int b = 0; b < 8; b++) acc[q][b] += w * sh[b*Hz + k];
                    }
                }
#pragma unroll
                for (int off = 16; off; off >>= 1)
#pragma unroll
                    for (int q = 0; q < 4; q++)
#pragma unroll
                        for (int b = 0; b < 8; b++) acc[q][b] += __shfl_xor_sync(~0u, acc[q][b], off);
                if (lane < 8){
                    int b = lane;
                    float gi = acc[0][b] + bih[j]        + bhh[j];
                    float gf = acc[1][b] + bih[Hz + j]   + bhh[Hz + j];
                    float gg = acc[2][b] + bih[2*Hz + j] + bhh[2*Hz + j];
                    float go = acc[3][b] + bih[3*Hz + j] + bhh[3*Hz + j];
                    float cn = sigmoidf_(gf)*__ldcg(&cin[b*Hz + j]) + sigmoidf_(gi)*tanhf(gg);
                    float hn = sigmoidf_(go)*tanhf(cn);
                    __stcg(&cout[b*Hz + j], cn);
                    __stcg(&hout[b*Hz + j], hn);
                }
            }
            gsync(&g_barA, (unsigned)(4*t + 1) * 64u);

            // ---- P2: hp ----
            {
                float* sh = sU;
                for (int i = tid; i < Bz*Hz; i += 256) sh[i] = __ldcg(&hout[i]);
                __syncthreads();
                int j = bid*8 + warp;
                const float* w = ew + (size_t)j*1024;
                float acc[8] = {};
#pragma unroll
                for (int i2 = 0; i2 < 16; i2++){
                    int k = lane + 32*i2; float wv = w[k];
#pragma unroll
                    for (int b = 0; b < 8; b++) acc[b] += wv * sh[b*Hz + k];
                }
#pragma unroll
                for (int off = 16; off; off >>= 1)
#pragma unroll
                    for (int b = 0; b < 8; b++) acc[b] += __shfl_xor_sync(~0u, acc[b], off);
                if (lane < 8) __stcg(&g_hp[lane*Hz + j], acc[lane]);
            }
            gsync(&g_barA, (unsigned)(4*t + 2) * 64u);

            // ---- P3: energies + zero ctx chunk ----
            {
                float* sh = sU;
                int b = bid >> 3, sc = bid & 7;
                for (int i = tid; i < Hz; i += 256){
                    sh[i]        = __ldcg(&g_hp[b*Hz + i]);
                    sh[Hz + i]   = covw[i];
                    sh[2*Hz + i] = vv[i];
                }
                if (tid < 64) __stcg(&ctxo[bid*64 + tid], 0.f);
                __syncthreads();
                int s0 = sc*50;
#pragma unroll
                for (int r = 0; r < 7; r++){
                    int sl = warp + 8*r;
                    if (sl < 50){
                        int s = s0 + sl;
                        float cb = __ldcg(&g_cov[b*Sz + s]);
                        const float* ep = g_encp + ((size_t)(b*Sz + s))*Hz;
                        float acc = 0.f;
#pragma unroll
                        for (int i2 = 0; i2 < 16; i2++){
                            int k = lane + 32*i2;
                            acc += sh[2*Hz + k] * tanhf(sh[k] + ep[k] + cb*sh[Hz + k]);
                        }
#pragma unroll
                        for (int off = 16; off; off >>= 1) acc += __shfl_xor_sync(~0u, acc, off);
                        if (lane == 0) __stcg(&g_e[b*Sz + s], acc);
                    }
                }
            }
            gsync(&g_barA, (unsigned)(4*t + 3) * 64u);

            // ---- P45: redundant softmax + slice writes + ctx partials ----
            {
                int b = bid >> 3, sc = bid & 7;
                float* se = sU;
                float* sp = sU + 512;
                se[tid] = __ldcg(&g_e[b*Sz + tid]);
                if (tid + 256 < Sz) se[tid + 256] = __ldcg(&g_e[b*Sz + tid + 256]);
                __syncthreads();
                float e0 = se[tid];
                float e1 = (tid + 256 < Sz) ? se[tid + 256] : -1e30f;
                float lm = fmaxf(e0, e1);
#pragma unroll
                for (int off = 16; off; off >>= 1) lm = fmaxf(lm, __shfl_xor_sync(~0u, lm, off));
                if (lane == 0) red[warp] = lm;
                __syncthreads();
                if (tid == 0){ float m = red[0]; for (int w = 1; w < 8; w++) m = fmaxf(m, red[w]); red[32] = m; }
                __syncthreads();
                float m = red[32];
                float x0 = expf(e0 - m);
                float x1 = (tid + 256 < Sz) ? expf(e1 - m) : 0.f;
                float ls = x0 + x1;
#pragma unroll
                for (int off = 16; off; off >>= 1) ls += __shfl_xor_sync(~0u, ls, off);
                if (lane == 0) red[warp] = ls;
                __syncthreads();
                if (tid == 0){ float s = 0.f; for (int w = 0; w < 8; w++) s += red[w]; red[33] = s; }
                __syncthreads();
                float s1 = red[33];
                float pm0 = x0/s1 * mask[b*Sz + tid];
                float pm1 = (tid + 256 < Sz) ? x1/s1 * mask[b*Sz + tid + 256] : 0.f;
                ls = pm0 + pm1;
#pragma unroll
                for (int off = 16; off; off >>= 1) ls += __shfl_xor_sync(~0u, ls, off);
                if (lane == 0) red[warp] = ls;
                __syncthreads();
                if (tid == 0){ float s = 0.f; for (int w = 0; w < 8; w++) s += red[w]; red[34] = s; }
                __syncthreads();
                float inv = 1.f/(red[34] + 1e-12f);
                if (tid < 50){
                    int s = sc*50 + tid;
                    float pr = expf(se[s] - m)/s1 * mask[b*Sz + s] * inv;
                    sp[tid] = pr;
                    __stcg(&pro[b*Sz + s], pr);
                    out[OUT_ATTN + ((size_t)b*Tz + t)*Sz + s] = pr;
                    float cn = __ldcg(&g_cov[b*Sz + s]) + pr;
                    __stcg(&g_cov[b*Sz + s], cn);
                    out[OUT_COV + ((size_t)b*Tz + t)*Sz + s] = cn;
                }
                __syncthreads();
                const float* eo = enc + ((size_t)(b*Sz) + sc*50)*Cz;
                float a0 = 0.f, a1 = 0.f;
#pragma unroll 10
                for (int s = 0; s < 50; s++){
                    float pv = sp[s];
                    a0 += pv * eo[(size_t)s*Cz + tid];
                    a1 += pv * eo[(size_t)s*Cz + tid + 256];
                }
                atomicAdd(&ctxo[b*Cz + tid], a0);
                atomicAdd(&ctxo[b*Cz + tid + 256], a1);
            }
            gsync(&g_barA, (unsigned)(4*t + 4) * 64u);

            // ---- P6: xnext (0..7) | pgen (8..15) | attnd (16..47) ----
            if (bid < 8){
                if (t + 1 < Tz){
                    int b = bid;
                    for (int i = tid; i < 512; i += 256) sU[128 + i] = __ldcg(&ctxo[b*Cz + i]);
                    if (tid < 128) sU[tid] = emb[((size_t)b*Tz + t + 1)*Ez + tid];
                    __syncthreads();
#pragma unroll
                    for (int q = 0; q < 16; q++){
                        int j = warp*16 + q;
                        const float* w = xw + (size_t)j*640;
                        float acc = 0.f;
#pragma unroll
                        for (int i2 = 0; i2 < 20; i2++){ int k = lane + 32*i2; acc += w[k]*sU[k]; }
#pragma unroll
                        for (int off = 16; off; off >>= 1) acc += __shfl_xor_sync(~0u, acc, off);
                        if (lane == 0) __stcg(&xout[b*Ez + j], acc + xb[j]);
                    }
                }
            } else if (bid < 16){
                int b = bid - 8;
                float z = __ldcg(&ctxo[b*Cz + tid])*pw[tid] + __ldcg(&ctxo[b*Cz + tid + 256])*pw[tid + 256]
                        + __ldcg(&hout[b*Hz + tid])*pw[512 + tid] + __ldcg(&hout[b*Hz + tid + 256])*pw[768 + tid];
                if (tid < 128) z += __ldcg(&xin[b*Ez + tid])*pw[1024 + tid];
#pragma unroll
                for (int off = 16; off; off >>= 1) z += __shfl_xor_sync(~0u, z, off);
                if (lane == 0) red[warp] = z;
                __syncthreads();
                if (tid == 0){
                    float s = 0.f; for (int w = 0; w < 8; w++) s += red[w];
                    float pg = sigmoidf_(s + pb[0]);
                    __stcg(&pgo[b], pg);
                    if (t == Tz - 1) out[OUT_PGEN + b] = pg;
                }
            } else if (bid < 48){
                int ab2 = bid - 16;
                int b = ab2 >> 2;
                for (int i = tid; i < 512; i += 256) sU[i]       = __ldcg(&hout[b*Hz + i]);
                for (int i = tid; i < 512; i += 256) sU[512 + i] = __ldcg(&ctxo[b*Cz + i]);
                __syncthreads();
                int r0 = (ab2 & 3)*128 + warp*16;
#pragma unroll
                for (int q = 0; q < 16; q++){
                    int j = r0 + q;
                    const float* w = aw + (size_t)j*1024;
                    float acc = 0.f;
#pragma unroll
                    for (int i2 = 0; i2 < 32; i2++){ int k = lane + 32*i2; acc += w[k]*sU[k]; }
#pragma unroll
                    for (int off = 16; off; off >>= 1) acc += __shfl_xor_sync(~0u, acc, off);
                    if (lane == 0) __stcg(&atd[b*Hz + j], acc + ab[j]);
                }
            }
        } else {
            if (bid < 16){
                int i = bid*256 + tid;
                out[OUT_CTX + i] = __ldcg(&g_ctx2[1][i]);
                out[OUT_H + i]   = __ldcg(&g_h2[1][i]);
                out[OUT_C + i]   = __ldcg(&g_c2[1][i]);
            }
        }
    } else {
        // =============== group V: vocab pipeline for u = t-1 (196 blocks, packed 16B loads) ===============
        if (t >= 1){
            int u = t - 1;
            int vbid = bid - 64;
            const float* pro = g_probs2[u & 1];
            const float* atd = g_attnd2[u & 1];
            const float* pgi = g_pgen2[u & 1];

            // Ph1: vocab GEMV (packed fp16, uint4 loads) + exp + sum
            float4* a4 = (float4*)sU;   // a4[b*128 + kk] = attnd[b][4kk..4kk+3]
            {
                const float4* src = (const float4*)atd;
#pragma unroll
                for (int r = 0; r < 4; r++) a4[tid + r*256] = __ldcg(&src[tid + r*256]);
            }
            __syncthreads();
            int j = vbid*256 + tid;
            bool valid = j < Vz;
            float acc[Bz];
            {
                float bj = valid ? vb[j] : 0.f;
#pragma unroll
                for (int b = 0; b < Bz; b++) acc[b] = bj;
            }
            {
                const uint4* wp = g_wt4 + (valid ? j : 0);
#pragma unroll 4
                for (int kg = 0; kg < 64; kg++){
                    uint4 w = *wp; wp += Vz;
                    const __half2* h = (const __half2*)&w;
                    float2 f0 = __half22float2(h[0]);
                    float2 f1 = __half22float2(h[1]);
                    float2 f2 = __half22float2(h[2]);
                    float2 f3 = __half22float2(h[3]);
#pragma unroll
                    for (int b = 0; b < Bz; b++){
                        float4 aA = a4[(size_t)b*128 + kg*2];
                        float4 aB = a4[(size_t)b*128 + kg*2 + 1];
                        acc[b] += f0.x*aA.x + f0.y*aA.y + f1.x*aA.z + f1.y*aA.w
                                + f2.x*aB.x + f2.y*aB.y + f3.x*aB.z + f3.y*aB.w;
                    }
                }
            }
#pragma unroll
            for (int b = 0; b < Bz; b++) acc[b] = valid ? expf(acc[b]) : 0.f;
#pragma unroll
            for (int b = 0; b < Bz; b++){
                float s = acc[b];
#pragma unroll
                for (int off = 16; off; off >>= 1) s += __shfl_xor_sync(~0u, s, off);
                if (lane == 0) red2[b][warp] = s;
            }
            __syncthreads();
            if (tid < 8){
                float s = 0.f;
#pragma unroll
                for (int w = 0; w < 8; w++) s += red2[tid][w];
                atomicAdd(&g_bsum[u][tid], s);
            }
            gsync(&g_barV, (unsigned)(u + 1) * 196u);

            // Ph2: atomic add of normalized dist + copy scatter
            if (tid < 8) smv[tid] = __ldcg(&pgi[tid]) / __ldcg(&g_bsum[u][tid]);
            __syncthreads();
            if (valid){
#pragma unroll
                for (int b = 0; b < Bz; b++)
                    atomicAdd(out + ((size_t)(b*Tz + u))*VEz + j, acc[b] * smv[b]);
            }
            if (vbid < 8){
                int b = vbid;
                float om = 1.f - __ldcg(&pgi[b]);
                float* row = out + ((size_t)(b*Tz + u))*VEz;
                for (int s = tid; s < Sz; s += 256)
                    atomicAdd(row + sidx[b*Sz + s], om * __ldcg(&pro[b*Sz + s]));
            }
        }
    }
}

extern "C" void kernel_launch(void* const* d_in, const int* in_sizes, int n_in,
                              void* d_out, int out_size){
    const float* emb   = (const float*)d_in[0];
    const float* ctx0  = (const float*)d_in[1];
    const float* h0    = (const float*)d_in[2];
    const float* c0    = (const float*)d_in[3];
    const float* enc   = (const float*)d_in[4];
    const float* mask  = (const float*)d_in[5];
    const int*   sidx  = (const int*)  d_in[7];
    const float* cov0  = (const float*)d_in[8];
    const float* Wih   = (const float*)d_in[9];
    const float* Whh   = (const float*)d_in[10];
    const float* bih   = (const float*)d_in[11];
    const float* bhh   = (const float*)d_in[12];
    const float* covw  = (const float*)d_in[13];
    const float* ew    = (const float*)d_in[14];
    const float* eb    = (const float*)d_in[15];
    const float* vvec  = (const float*)d_in[16];
    const float* xw    = (const float*)d_in[17];
    const float* xb    = (const float*)d_in[18];
    const float* aw    = (const float*)d_in[19];
    const float* ab    = (const float*)d_in[20];
    const float* vw    = (const float*)d_in[21];
    const float* vb    = (const float*)d_in[22];
    const float* pw    = (const float*)d_in[23];
    const float* pb    = (const float*)d_in[24];
    float* out = (float*)d_out;

    k_init<<<32, 512>>>(h0, c0, ctx0, cov0);
    k_pre<<<368, 256>>>(enc, ew, eb, vw, emb, xw, xb, out);

    for (int t = 0; t <= Tz; t++){
        k_step<<<260, 256>>>(Wih, Whh, bih, bhh, ew, covw, vvec, enc, mask,
                             aw, ab, pw, pb, xw, xb, emb, vb, sidx, out, t);
    }
}

// round 11
// speedup vs baseline: 1.2230x; 1.1961x over previous
#include <cuda_runtime.h>
#include <cuda_fp16.h>
#include <math.h>

#define Bz 8
#define Tz 16
#define Sz 400
#define Hz 512
#define Cz 512
#define Ez 128
#define Vz 50000
#define VEz 50050

#define OUT_CTX  (Bz*Tz*VEz)
#define OUT_H    (OUT_CTX + Bz*Cz)
#define OUT_C    (OUT_H + Bz*Hz)
#define OUT_ATTN (OUT_C + Bz*Hz)
#define OUT_PGEN (OUT_ATTN + Bz*Tz*Sz)
#define OUT_COV  (OUT_PGEN + Bz)

// ---- device scratch ----
__device__ uint4 g_wt4[(size_t)(Hz/8)*Vz];   // packed fp16 vocab weights
__device__ float g_encp[Bz*Sz*Hz];           // enc @ ew[:,H:]^T + eb
__device__ float g_encx[Bz*Sz*Ez];           // enc @ xw[:,128:]^T
__device__ float g_embx[Bz*Tz*Ez];           // emb @ xw[:,:128]^T + xb
__device__ float g_h2[2][Bz*Hz];
__device__ float g_c2[2][Bz*Hz];
__device__ float g_x3[3][Bz*Ez];
__device__ float g_ctx2[2][Bz*Cz];
__device__ float g_probs2[2][Bz*Sz];
__device__ float g_attnd[Bz*Hz];
__device__ float g_pgen[Bz];
__device__ float g_cov[Bz*Sz];
__device__ float g_hp[Bz*Hz];
__device__ float g_e[Bz*Sz];
__device__ float g_bsum[Tz][Bz];
__device__ unsigned g_barA, g_barV;

__device__ __forceinline__ float sigmoidf_(float x){ return 1.f/(1.f+expf(-x)); }

// grid-subgroup barrier, CG-style: syncthreads (cumulative HB) -> t0 release-add -> acquire-poll
__device__ __forceinline__ void gsync(unsigned* bar, unsigned target){
    __syncthreads();
    if (threadIdx.x == 0){
        asm volatile("red.release.gpu.global.add.u32 [%0], %1;" :: "l"(bar), "r"(1u) : "memory");
        unsigned v;
        for (;;){
            asm volatile("ld.acquire.gpu.global.u32 %0, [%1];" : "=r"(v) : "l"(bar) : "memory");
            if (v >= target) break;
            __nanosleep(32);
        }
    }
    __syncthreads();
}

// ---- init ----
__global__ void k_init(const float* __restrict__ h0, const float* __restrict__ c0,
                       const float* __restrict__ ctx, const float* __restrict__ cov){
    int i = blockIdx.x*blockDim.x + threadIdx.x;
    if (i < Bz*Hz){ g_h2[1][i] = h0[i]; g_c2[1][i] = c0[i]; }
    if (i < Bz*Cz)  g_ctx2[1][i] = ctx[i];
    if (i < Bz*Sz)  g_cov[i] = cov[i];
    if (i == 0){ g_barA = 0u; g_barV = 0u; }
    if (i < Tz*Bz) ((float*)g_bsum)[i] = 0.f;
}

// ==== fused precompute ====
// 0..199 encproj | 200..303 transpose->packed fp16 | 304..335 zero | 336..367 x0
// 368..417 encx GEMM | 418..433 embx
__global__ __launch_bounds__(256) void k_pre(const float* __restrict__ enc,
                                             const float* __restrict__ ew,
                                             const float* __restrict__ eb,
                                             const float* __restrict__ vw,
                                             const float* __restrict__ emb,
                                             const float* __restrict__ xw,
                                             const float* __restrict__ xb,
                                             float* __restrict__ out){
    int tid = threadIdx.x, bid = blockIdx.x;
    if (bid < 200 || (bid >= 368 && bid < 418)){
        // tiled GEMM: A=enc[3200,512]; B rows from ew (N=512, off 512, len 1024) or xw (N=128, off 128, len 640)
        bool isx = bid >= 368;
        int lbid = isx ? bid - 368 : bid;
        int bm = (lbid % 25) * 128;
        int bn = (lbid / 25) * 64;
        const float* wsrc = isx ? xw : ew;
        int wlen = isx ? 640 : 1024;
        int woff = isx ? 128 : 512;
        __shared__ float As[16][128];
        __shared__ float Bs[16][64];
        float acc[8][4] = {};
        for (int k0 = 0; k0 < 512; k0 += 16){
#pragma unroll
            for (int r = 0; r < 2; r++){
                int id = tid + r*256;
                int m  = id >> 2;
                int kq = (id & 3) * 4;
                float4 v = *(const float4*)(enc + (size_t)(bm+m)*512 + k0 + kq);
                As[kq  ][m] = v.x; As[kq+1][m] = v.y; As[kq+2][m] = v.z; As[kq+3][m] = v.w;
            }
            {
                int n  = tid >> 2;
                int kq = (tid & 3) * 4;
                float4 v = *(const float4*)(wsrc + (size_t)(bn+n)*wlen + woff + k0 + kq);
                Bs[kq  ][n] = v.x; Bs[kq+1][n] = v.y; Bs[kq+2][n] = v.z; Bs[kq+3][n] = v.w;
            }
            __syncthreads();
            int tm = (tid >> 4) * 8, tn = (tid & 15) * 4;
#pragma unroll
            for (int kk = 0; kk < 16; kk++){
                float a[8], bb[4];
                *(float4*)&a[0] = *(const float4*)&As[kk][tm];
                *(float4*)&a[4] = *(const float4*)&As[kk][tm+4];
                *(float4*)&bb[0] = *(const float4*)&Bs[kk][tn];
#pragma unroll
                for (int i = 0; i < 8; i++)
#pragma unroll
                    for (int j = 0; j < 4; j++) acc[i][j] += a[i]*bb[j];
            }
            __syncthreads();
        }
        int tm = (tid >> 4) * 8, tn = (tid & 15) * 4;
        if (isx){
#pragma unroll
            for (int i = 0; i < 8; i++)
#pragma unroll
                for (int j = 0; j < 4; j++)
                    g_encx[(size_t)(bm+tm+i)*128 + bn+tn+j] = acc[i][j];
        } else {
#pragma unroll
            for (int i = 0; i < 8; i++)
#pragma unroll
                for (int j = 0; j < 4; j++)
                    g_encp[(size_t)(bm+tm+i)*512 + bn+tn+j] = acc[i][j] + eb[bn+tn+j];
        }
    } else if (bid < 304){
        // transpose vocab_w fp32 -> packed fp16 g_wt4
        __shared__ float tile[32][33];
        int tx = tid & 31, ty = tid >> 5;
        const int NTILE = ((Vz + 31)/32) * (Hz/32);
        for (int T = bid - 200; T < NTILE; T += 104){
            int jb = (T % 1563)*32, kb = (T / 1563)*32;
            __syncthreads();
#pragma unroll
            for (int r = 0; r < 32; r += 8){
                int jj = jb + ty + r;
                if (jj < Vz) tile[ty + r][tx] = vw[(size_t)jj*Hz + kb + tx];
            }
            __syncthreads();
            if (tid < 128){
                int jl = tid & 31, kgl = tid >> 5;
                int jj = jb + jl;
                if (jj < Vz){
                    __half hv[8];
#pragma unroll
                    for (int r = 0; r < 8; r++) hv[r] = __float2half(tile[jl][kgl*8 + r]);
                    g_wt4[((size_t)(kb/8) + kgl)*Vz + jj] = *(const uint4*)hv;
                }
            }
        }
    } else if (bid < 336){
        float4* o4 = (float4*)out;
        for (size_t i = (size_t)(bid - 304)*256 + tid; i < (size_t)Bz*Tz*VEz/4; i += 32*256)
            o4[i] = make_float4(0.f,0.f,0.f,0.f);
    } else if (bid < 368){
        // x0 (full GEMV from [emb(b,0), ctx0])
        int xbid = bid - 336;
        int b = xbid >> 2;
        int warp = tid >> 5, lane = tid & 31;
        __shared__ float vec[640];
        for (int i = tid; i < 128; i += 256) vec[i] = emb[(size_t)b*Tz*Ez + i];
        for (int i = tid; i < 512; i += 256) vec[128 + i] = g_ctx2[1][b*Cz + i];
        __syncthreads();
#pragma unroll
        for (int q = 0; q < 4; q++){
            int j = (xbid & 3)*32 + warp*4 + q;
            const float* w = xw + (size_t)j*640;
            float acc = 0.f;
#pragma unroll
            for (int i = 0; i < 20; i++){ int k = lane + 32*i; acc += w[k]*vec[k]; }
#pragma unroll
            for (int off = 16; off; off >>= 1) acc += __shfl_xor_sync(~0u, acc, off);
            if (lane == 0) g_x3[0][b*Ez + j] = acc + xb[j];
        }
    } else {
        // embx: [8,16,128] = emb @ xw[:, :128]^T + xb ; block q: b=q>>1, warp w -> t=(q&1)*8+w
        int q = bid - 418;
        int b = q >> 1;
        int warp = tid >> 5, lane = tid & 31;
        int tt = (q & 1)*8 + warp;
        float ev[4];
#pragma unroll
        for (int i = 0; i < 4; i++) ev[i] = emb[((size_t)b*Tz + tt)*Ez + lane + 32*i];
        for (int j = 0; j < 128; j++){
            const float* w = xw + (size_t)j*640;
            float acc = 0.f;
#pragma unroll
            for (int i = 0; i < 4; i++) acc += w[lane + 32*i]*ev[i];
#pragma unroll
            for (int off = 16; off; off >>= 1) acc += __shfl_xor_sync(~0u, acc, off);
            if (lane == 0) g_embx[((size_t)b*Tz + tt)*Ez + j] = acc + xb[j];
        }
    }
}

// ==== pipelined step kernel: blocks 0..63 = A(t); 64..259 = V(t-1) ====
__global__ __launch_bounds__(256, 2) void k_step(
        const float* __restrict__ Wih, const float* __restrict__ Whh,
        const float* __restrict__ bih, const float* __restrict__ bhh,
        const float* __restrict__ ew,  const float* __restrict__ covw,
        const float* __restrict__ vv,  const float* __restrict__ enc,
        const float* __restrict__ mask,
        const float* __restrict__ aw,  const float* __restrict__ ab,
        const float* __restrict__ pw,  const float* __restrict__ pb,
        const float* __restrict__ vb,
        const int*   __restrict__ sidx,
        float* __restrict__ out, int t){
    __shared__ __align__(16) float sU[5248];
    __shared__ float red[40];
    __shared__ float red2[8][8];
    __shared__ float smv[8];
    int tid = threadIdx.x, warp = tid >> 5, lane = tid & 31, bid = blockIdx.x;

    if (bid < 64){
        // =============== group A: recurrence step t (4 phases, 3 barriers) ===============
        if (t < Tz){
            const float* xin  = g_x3[t % 3];
            float*       xout = g_x3[(t + 1) % 3];
            const float* hin  = g_h2[(t + 1) & 1];
            float*       hout = g_h2[t & 1];
            const float* cin  = g_c2[(t + 1) & 1];
            float*       cout = g_c2[t & 1];
            float*       ctxo = g_ctx2[t & 1];
            float*       pro  = g_probs2[t & 1];

            // ---- P1: gates + LSTM elementwise ----
            {
                float* sx = sU;
                float* sh = sU + 1024;
                for (int i = tid; i < Bz*Ez; i += 256) sx[i] = __ldcg(&xin[i]);
                for (int i = tid; i < Bz*Hz; i += 256) sh[i] = __ldcg(&hin[i]);
                __syncthreads();
                int j = bid*8 + warp;
                float acc[4][8] = {};
#pragma unroll
                for (int q = 0; q < 4; q++){
                    const float* wi = Wih + (size_t)(q*Hz + j)*Ez;
#pragma unroll
                    for (int i2 = 0; i2 < 4; i2++){
                        int k = lane + 32*i2; float w = wi[k];
#pragma unroll
                        for (int b = 0; b < 8; b++) acc[q][b] += w * sx[b*Ez + k];
                    }
                    const float* wh = Whh + (size_t)(q*Hz + j)*Hz;
#pragma unroll
                    for (int i2 = 0; i2 < 16; i2++){
                        int k = lane + 32*i2; float w = wh[k];
#pragma unroll
                        for (int b = 0; b < 8; b++) acc[q][b] += w * sh[b*Hz + k];
                    }
                }
#pragma unroll
                for (int off = 16; off; off >>= 1)
#pragma unroll
                    for (int q = 0; q < 4; q++)
#pragma unroll
                        for (int b = 0; b < 8; b++) acc[q][b] += __shfl_xor_sync(~0u, acc[q][b], off);
                if (lane < 8){
                    int b = lane;
                    float gi = acc[0][b] + bih[j]        + bhh[j];
                    float gf = acc[1][b] + bih[Hz + j]   + bhh[Hz + j];
                    float gg = acc[2][b] + bih[2*Hz + j] + bhh[2*Hz + j];
                    float go = acc[3][b] + bih[3*Hz + j] + bhh[3*Hz + j];
                    float cn = sigmoidf_(gf)*__ldcg(&cin[b*Hz + j]) + sigmoidf_(gi)*tanhf(gg);
                    float hn = sigmoidf_(go)*tanhf(cn);
                    __stcg(&cout[b*Hz + j], cn);
                    __stcg(&hout[b*Hz + j], hn);
                }
            }
            gsync(&g_barA, (unsigned)(3*t + 1) * 64u);

            // ---- P2: hp ----
            {
                float* sh = sU;
                for (int i = tid; i < Bz*Hz; i += 256) sh[i] = __ldcg(&hout[i]);
                __syncthreads();
                int j = bid*8 + warp;
                const float* w = ew + (size_t)j*1024;
                float acc[8] = {};
#pragma unroll
                for (int i2 = 0; i2 < 16; i2++){
                    int k = lane + 32*i2; float wv = w[k];
#pragma unroll
                    for (int b = 0; b < 8; b++) acc[b] += wv * sh[b*Hz + k];
                }
#pragma unroll
                for (int off = 16; off; off >>= 1)
#pragma unroll
                    for (int b = 0; b < 8; b++) acc[b] += __shfl_xor_sync(~0u, acc[b], off);
                if (lane < 8) __stcg(&g_hp[lane*Hz + j], acc[lane]);
            }
            gsync(&g_barA, (unsigned)(3*t + 2) * 64u);

            // ---- P3: energies + zero ctx chunk + init xout with embx ----
            {
                float* sh = sU;
                int b = bid >> 3, sc = bid & 7;
                for (int i = tid; i < Hz; i += 256){
                    sh[i]        = __ldcg(&g_hp[b*Hz + i]);
                    sh[Hz + i]   = covw[i];
                    sh[2*Hz + i] = vv[i];
                }
                if (tid < 64) __stcg(&ctxo[bid*64 + tid], 0.f);
                if (sc == 0 && tid < 128 && t + 1 < Tz)
                    __stcg(&xout[b*Ez + tid], g_embx[((size_t)b*Tz + t + 1)*Ez + tid]);
                __syncthreads();
                int s0 = sc*50;
#pragma unroll
                for (int r = 0; r < 7; r++){
                    int sl = warp + 8*r;
                    if (sl < 50){
                        int s = s0 + sl;
                        float cb = __ldcg(&g_cov[b*Sz + s]);
                        const float* ep = g_encp + ((size_t)(b*Sz + s))*Hz;
                        float acc = 0.f;
#pragma unroll
                        for (int i2 = 0; i2 < 16; i2++){
                            int k = lane + 32*i2;
                            acc += sh[2*Hz + k] * tanhf(sh[k] + ep[k] + cb*sh[Hz + k]);
                        }
#pragma unroll
                        for (int off = 16; off; off >>= 1) acc += __shfl_xor_sync(~0u, acc, off);
                        if (lane == 0) __stcg(&g_e[b*Sz + s], acc);
                    }
                }
            }
            gsync(&g_barA, (unsigned)(3*t + 3) * 64u);

            // ---- P45: redundant softmax + slice writes + ctx partials + xnext partials ----
            {
                int b = bid >> 3, sc = bid & 7;
                float* se = sU;
                float* sp = sU + 512;
                se[tid] = __ldcg(&g_e[b*Sz + tid]);
                if (tid + 256 < Sz) se[tid + 256] = __ldcg(&g_e[b*Sz + tid + 256]);
                __syncthreads();
                float e0 = se[tid];
                float e1 = (tid + 256 < Sz) ? se[tid + 256] : -1e30f;
                float lm = fmaxf(e0, e1);
#pragma unroll
                for (int off = 16; off; off >>= 1) lm = fmaxf(lm, __shfl_xor_sync(~0u, lm, off));
                if (lane == 0) red[warp] = lm;
                __syncthreads();
                if (tid == 0){ float m = red[0]; for (int w = 1; w < 8; w++) m = fmaxf(m, red[w]); red[32] = m; }
                __syncthreads();
                float m = red[32];
                float x0 = expf(e0 - m);
                float x1 = (tid + 256 < Sz) ? expf(e1 - m) : 0.f;
                float ls = x0 + x1;
#pragma unroll
                for (int off = 16; off; off >>= 1) ls += __shfl_xor_sync(~0u, ls, off);
                if (lane == 0) red[warp] = ls;
                __syncthreads();
                if (tid == 0){ float s = 0.f; for (int w = 0; w < 8; w++) s += red[w]; red[33] = s; }
                __syncthreads();
                float s1 = red[33];
                float pm0 = x0/s1 * mask[b*Sz + tid];
                float pm1 = (tid + 256 < Sz) ? x1/s1 * mask[b*Sz + tid + 256] : 0.f;
                ls = pm0 + pm1;
#pragma unroll
                for (int off = 16; off; off >>= 1) ls += __shfl_xor_sync(~0u, ls, off);
                if (lane == 0) red[warp] = ls;
                __syncthreads();
                if (tid == 0){ float s = 0.f; for (int w = 0; w < 8; w++) s += red[w]; red[34] = s; }
                __syncthreads();
                float inv = 1.f/(red[34] + 1e-12f);
                if (tid < 50){
                    int s = sc*50 + tid;
                    float pr = expf(se[s] - m)/s1 * mask[b*Sz + s] * inv;
                    sp[tid] = pr;
                    __stcg(&pro[b*Sz + s], pr);
                    out[OUT_ATTN + ((size_t)b*Tz + t)*Sz + s] = pr;
                    float cn = __ldcg(&g_cov[b*Sz + s]) + pr;
                    __stcg(&g_cov[b*Sz + s], cn);
                    out[OUT_COV + ((size_t)b*Tz + t)*Sz + s] = cn;
                }
                __syncthreads();
                const float* eo = enc + ((size_t)(b*Sz) + sc*50)*Cz;
                float a0 = 0.f, a1 = 0.f;
#pragma unroll 10
                for (int s = 0; s < 50; s++){
                    float pv = sp[s];
                    a0 += pv * eo[(size_t)s*Cz + tid];
                    a1 += pv * eo[(size_t)s*Cz + tid + 256];
                }
                atomicAdd(&ctxo[b*Cz + tid], a0);
                atomicAdd(&ctxo[b*Cz + tid + 256], a1);
                // xnext partials via encx
                if (t + 1 < Tz && tid < 128){
                    const float* ex = g_encx + ((size_t)(b*Sz) + sc*50)*Ez + tid;
                    float a = 0.f;
#pragma unroll 10
                    for (int s = 0; s < 50; s++) a += sp[s] * ex[(size_t)s*Ez];
                    atomicAdd(&xout[b*Ez + tid], a);
                }
            }
            // (no barrier — launch boundary completes A(t))
        } else {
            // t == Tz: final states
            if (bid < 16){
                int i = bid*256 + tid;
                out[OUT_CTX + i] = __ldcg(&g_ctx2[1][i]);
                out[OUT_H + i]   = __ldcg(&g_h2[1][i]);
                out[OUT_C + i]   = __ldcg(&g_c2[1][i]);
            }
        }
    } else {
        // =============== group V: vocab pipeline for u = t-1 ===============
        if (t >= 1){
            int u = t - 1;
            int vbid = bid - 64;
            const float* pro = g_probs2[u & 1];
            const float* h   = g_h2[u & 1];
            const float* ctx = g_ctx2[u & 1];
            const float* xu  = g_x3[u % 3];

            // ---- Ph0: attnd (vbid 0..127) | pgen (vbid 128..135) ----
            if (vbid < 128){
                int b = vbid >> 4;
                for (int i = tid; i < 512; i += 256) sU[i]       = __ldcg(&h[b*Hz + i]);
                for (int i = tid; i < 512; i += 256) sU[512 + i] = __ldcg(&ctx[b*Cz + i]);
                __syncthreads();
                int r0 = (vbid & 15)*32 + warp*4;
#pragma unroll
                for (int q = 0; q < 4; q++){
                    int j = r0 + q;
                    const float* w = aw + (size_t)j*1024;
                    float acc = 0.f;
#pragma unroll
                    for (int i2 = 0; i2 < 32; i2++){ int k = lane + 32*i2; acc += w[k]*sU[k]; }
#pragma unroll
                    for (int off = 16; off; off >>= 1) acc += __shfl_xor_sync(~0u, acc, off);
                    if (lane == 0) __stcg(&g_attnd[b*Hz + j], acc + ab[j]);
                }
            } else if (vbid < 136){
                int b = vbid - 128;
                float z = __ldcg(&ctx[b*Cz + tid])*pw[tid] + __ldcg(&ctx[b*Cz + tid + 256])*pw[tid + 256]
                        + __ldcg(&h[b*Hz + tid])*pw[512 + tid] + __ldcg(&h[b*Hz + tid + 256])*pw[768 + tid];
                if (tid < 128) z += __ldcg(&xu[b*Ez + tid])*pw[1024 + tid];
#pragma unroll
                for (int off = 16; off; off >>= 1) z += __shfl_xor_sync(~0u, z, off);
                if (lane == 0) red[warp] = z;
                __syncthreads();
                if (tid == 0){
                    float s = 0.f; for (int w = 0; w < 8; w++) s += red[w];
                    float pg = sigmoidf_(s + pb[0]);
                    __stcg(&g_pgen[b], pg);
                    if (u == Tz - 1) out[OUT_PGEN + b] = pg;
                }
            }
            gsync(&g_barV, (unsigned)(2*u + 1) * 196u);

            // ---- Ph1: vocab GEMV (packed fp16, uint4) + exp + sum ----
            float4* a4 = (float4*)sU;
            {
                const float4* src = (const float4*)g_attnd;
#pragma unroll
                for (int r = 0; r < 4; r++) a4[tid + r*256] = __ldcg(&src[tid + r*256]);
            }
            __syncthreads();
            int j = vbid*256 + tid;
            bool valid = j < Vz;
            float acc[Bz];
            {
                float bj = valid ? vb[j] : 0.f;
#pragma unroll
                for (int b = 0; b < Bz; b++) acc[b] = bj;
            }
            {
                const uint4* wp = g_wt4 + (valid ? j : 0);
#pragma unroll 4
                for (int kg = 0; kg < 64; kg++){
                    uint4 w = *wp; wp += Vz;
                    const __half2* hh = (const __half2*)&w;
                    float2 f0 = __half22float2(hh[0]);
                    float2 f1 = __half22float2(hh[1]);
                    float2 f2 = __half22float2(hh[2]);
                    float2 f3 = __half22float2(hh[3]);
#pragma unroll
                    for (int b = 0; b < Bz; b++){
                        float4 aA = a4[(size_t)b*128 + kg*2];
                        float4 aB = a4[(size_t)b*128 + kg*2 + 1];
                        acc[b] += f0.x*aA.x + f0.y*aA.y + f1.x*aA.z + f1.y*aA.w
                                + f2.x*aB.x + f2.y*aB.y + f3.x*aB.z + f3.y*aB.w;
                    }
                }
            }
#pragma unroll
            for (int b = 0; b < Bz; b++) acc[b] = valid ? expf(acc[b]) : 0.f;
#pragma unroll
            for (int b = 0; b < Bz; b++){
                float s = acc[b];
#pragma unroll
                for (int off = 16; off; off >>= 1) s += __shfl_xor_sync(~0u, s, off);
                if (lane == 0) red2[b][warp] = s;
            }
            __syncthreads();
            if (tid < 8){
                float s = 0.f;
#pragma unroll
                for (int w = 0; w < 8; w++) s += red2[tid][w];
                atomicAdd(&g_bsum[u][tid], s);
            }
            gsync(&g_barV, (unsigned)(2*u + 2) * 196u);

            // ---- Ph2: atomic add of normalized dist + copy scatter ----
            if (tid < 8) smv[tid] = __ldcg(&g_pgen[tid]) / __ldcg(&g_bsum[u][tid]);
            __syncthreads();
            if (valid){
#pragma unroll
                for (int b = 0; b < Bz; b++)
                    atomicAdd(out + ((size_t)(b*Tz + u))*VEz + j, acc[b] * smv[b]);
            }
            if (vbid < 8){
                int b = vbid;
                float om = 1.f - __ldcg(&g_pgen[b]);
                float* row = out + ((size_t)(b*Tz + u))*VEz;
                for (int s = tid; s < Sz; s += 256)
                    atomicAdd(row + sidx[b*Sz + s], om * __ldcg(&pro[b*Sz + s]));
            }
        }
    }
}

extern "C" void kernel_launch(void* const* d_in, const int* in_sizes, int n_in,
                              void* d_out, int out_size){
    const float* emb   = (const float*)d_in[0];
    const float* ctx0  = (const float*)d_in[1];
    const float* h0    = (const float*)d_in[2];
    const float* c0    = (const float*)d_in[3];
    const float* enc   = (const float*)d_in[4];
    const float* mask  = (const float*)d_in[5];
    const int*   sidx  = (const int*)  d_in[7];
    const float* cov0  = (const float*)d_in[8];
    const float* Wih   = (const float*)d_in[9];
    const float* Whh   = (const float*)d_in[10];
    const float* bih   = (const float*)d_in[11];
    const float* bhh   = (const float*)d_in[12];
    const float* covw  = (const float*)d_in[13];
    const float* ew    = (const float*)d_in[14];
    const float* eb    = (const float*)d_in[15];
    const float* vvec  = (const float*)d_in[16];
    const float* xw    = (const float*)d_in[17];
    const float* xb    = (const float*)d_in[18];
    const float* aw    = (const float*)d_in[19];
    const float* ab    = (const float*)d_in[20];
    const float* vw    = (const float*)d_in[21];
    const float* vb    = (const float*)d_in[22];
    const float* pw    = (const float*)d_in[23];
    const float* pb    = (const float*)d_in[24];
    float* out = (float*)d_out;

    k_init<<<32, 512>>>(h0, c0, ctx0, cov0);
    k_pre<<<434, 256>>>(enc, ew, eb, vw, emb, xw, xb, out);

    for (int t = 0; t <= Tz; t++){
        k_step<<<260, 256>>>(Wih, Whh, bih, bhh, ew, covw, vvec, enc, mask,
                             aw, ab, pw, pb, vb, sidx, out, t);
    }
}